// round 13
// baseline (speedup 1.0000x reference)
#include <cuda_runtime.h>
#include <cuda_fp16.h>
#include <math.h>
#include <stdint.h>

#define BB   2
#define TT   2048
#define CC   2048
#define HH   32
#define KVHN 8
#define DD   64
#define KDIM 2048

// GEMM tile config (fp16, BK=64)
#define GBM  128
#define GBN  128
#define GBK  64
#define NCHUNK (KDIM / GBK)       // 32
#define HSTR 72                   // smem row stride in halves (144 B, ldmatrix conflict-free)
#define TILE_B (128 * HSTR * 2)   // 18432 B per operand tile
#define GEMM_SMEM (3 * 2 * TILE_B)  // 3-stage: 110592 B
#define PT 136                    // transpose-staging stride (halves); 272 B, 16B-aligned

// Scratch (allocation-free rule: __device__ globals)
__device__ __half g_q[(size_t)BB * TT * CC];
__device__ __half g_k[(size_t)BB * TT * KVHN * DD];
__device__ __half g_vT[(size_t)BB * KVHN * DD * TT];
__device__ __half g_attn[(size_t)BB * TT * CC];
// fp16 pre-rounded operand copies
__device__ __half g_xt [(size_t)BB * TT * CC];
__device__ __half g_wqt[(size_t)CC * CC];
__device__ __half g_wkt[(size_t)KVHN * DD * CC];
__device__ __half g_wvt[(size_t)KVHN * DD * CC];
__device__ __half g_wot[(size_t)CC * CC];

// ---------------------------------------------------------------------------
// helpers
// ---------------------------------------------------------------------------
__device__ __forceinline__ uint32_t smem_u32(const void* p) {
    uint32_t r;
    asm("{ .reg .u64 t; cvta.to.shared.u64 t, %1; cvt.u32.u64 %0, t; }" : "=r"(r) : "l"(p));
    return r;
}
__device__ __forceinline__ uint32_t pack_h2(float a, float b) {
    __half2 h = __floats2half2_rn(a, b);
    return *reinterpret_cast<uint32_t*>(&h);
}
#define CP16(dst, src) \
    asm volatile("cp.async.cg.shared.global [%0], [%1], 16;" :: "r"(dst), "l"(src))
#define CP_COMMIT() asm volatile("cp.async.commit_group;" ::: "memory")
#define CP_WAITG1() asm volatile("cp.async.wait_group 1;" ::: "memory")
#define CP_WAIT0()  asm volatile("cp.async.wait_group 0;" ::: "memory")

#define LDMX4(r0, r1, r2, r3, addr) \
    asm volatile("ldmatrix.sync.aligned.m8n8.x4.shared.b16 {%0,%1,%2,%3}, [%4];" \
        : "=r"(r0), "=r"(r1), "=r"(r2), "=r"(r3) : "r"(addr))

__device__ __forceinline__ void mma_f16(float* d, const uint32_t* a, const uint32_t* b) {
    asm volatile(
        "mma.sync.aligned.m16n8k16.row.col.f32.f16.f16.f32 "
        "{%0,%1,%2,%3}, {%4,%5,%6,%7}, {%8,%9}, {%0,%1,%2,%3};"
        : "+f"(d[0]), "+f"(d[1]), "+f"(d[2]), "+f"(d[3])
        : "r"(a[0]), "r"(a[1]), "r"(a[2]), "r"(a[3]), "r"(b[0]), "r"(b[1]));
}

// ---------------------------------------------------------------------------
// Fused fp16 pre-rounding copy (x, Wq, Wk, Wv, Wo in one launch)
// ---------------------------------------------------------------------------
#define N4_X  (BB * TT * CC / 4)
#define N4_WQ (CC * CC / 4)
#define N4_WK (KVHN * DD * CC / 4)

__global__ void round_copy_all(const float4* __restrict__ x,  uint2* __restrict__ xt,
                               const float4* __restrict__ wq, uint2* __restrict__ wqt,
                               const float4* __restrict__ wk, uint2* __restrict__ wkt,
                               const float4* __restrict__ wv, uint2* __restrict__ wvt,
                               const float4* __restrict__ wo, uint2* __restrict__ wot)
{
    int i = blockIdx.x * blockDim.x + threadIdx.x;
    const float4* in; uint2* out; int j = i;
    if (j < N4_X)                      { in = x;  out = xt; }
    else if ((j -= N4_X) < N4_WQ)      { in = wq; out = wqt; }
    else if ((j -= N4_WQ) < N4_WK)     { in = wk; out = wkt; }
    else if ((j -= N4_WK) < N4_WK)     { in = wv; out = wvt; }
    else if ((j -= N4_WK) < N4_WQ)     { in = wo; out = wot; }
    else return;
    float4 v = in[j];
    uint2 o;
    o.x = pack_h2(v.x, v.y);
    o.y = pack_h2(v.z, v.w);
    out[j] = o;
}

// ---------------------------------------------------------------------------
// fp16 mma.sync NT GEMM tile: BK=64, 3-stage cp.async, ldmatrix loads.
// Mode 0: fp32 out.  Mode 1: fp16 out.  Mode 2: fp16 TRANSPOSED out
//   (Cp points at vT tile base; ldc = TT; writes C[n_local*ldc + t_local]).
// ---------------------------------------------------------------------------
template<int Mode>
__device__ __forceinline__ void gemm_mma_tile(const __half* __restrict__ A,
                                              const __half* __restrict__ W,
                                              void* __restrict__ Cp, int ldc)
{
    extern __shared__ float smf[];
    const uint32_t sbase = smem_u32(smf);

    const int tid  = threadIdx.x;
    const int wid  = tid >> 5, lane = tid & 31;
    const int wm   = wid & 1,  wn   = wid >> 1;
    const int g    = lane >> 2, tig = lane & 3;

    const int lrowA  = lane & 15;
    const int lcolA  = (lane >> 4) * 16;                      // bytes
    const int lrowB  = (lane & 7) + ((lane >> 4) << 3);
    const int lcolB  = (lane & 8) ? 16 : 0;                   // bytes

    float acc[4][4][4];
#pragma unroll
    for (int i = 0; i < 4; ++i)
#pragma unroll
        for (int j = 0; j < 4; ++j)
#pragma unroll
            for (int e = 0; e < 4; ++e) acc[i][j][e] = 0.f;

    auto load_chunk = [&](int c, int buf) {
        const __half* Ab = A + c * GBK;
        const __half* Wb = W + c * GBK;
        const uint32_t da = sbase + (uint32_t)buf * 2u * TILE_B;
        const uint32_t db = da + TILE_B;
#pragma unroll
        for (int i = 0; i < 4; ++i) {
            int lin = tid + i * 256;
            int r = lin >> 3, c8 = lin & 7;
            CP16(da + (uint32_t)(r * HSTR + c8 * 8) * 2u,
                 Ab + (size_t)r * KDIM + c8 * 8);
        }
#pragma unroll
        for (int i = 0; i < 4; ++i) {
            int lin = tid + i * 256;
            int r = lin >> 3, c8 = lin & 7;
            CP16(db + (uint32_t)(r * HSTR + c8 * 8) * 2u,
                 Wb + (size_t)r * KDIM + c8 * 8);
        }
        CP_COMMIT();
    };

    auto compute = [&](int buf) {
        const uint32_t abase = sbase + (uint32_t)buf * 2u * TILE_B;
        const uint32_t bbase = abase + TILE_B;
        uint32_t aaddr[4], baddr[2];
#pragma unroll
        for (int mf = 0; mf < 4; ++mf)
            aaddr[mf] = abase + (uint32_t)((wm * 64 + mf * 16 + lrowA) * HSTR) * 2u + lcolA;
#pragma unroll
        for (int np = 0; np < 2; ++np)
            baddr[np] = bbase + (uint32_t)((wn * 32 + np * 16 + lrowB) * HSTR) * 2u + lcolB;

#pragma unroll
        for (int ks = 0; ks < 4; ++ks) {
            uint32_t a[4][4], b2[2][4];
#pragma unroll
            for (int mf = 0; mf < 4; ++mf)
                LDMX4(a[mf][0], a[mf][1], a[mf][2], a[mf][3], aaddr[mf] + ks * 32);
#pragma unroll
            for (int np = 0; np < 2; ++np)
                LDMX4(b2[np][0], b2[np][1], b2[np][2], b2[np][3], baddr[np] + ks * 32);
#pragma unroll
            for (int mf = 0; mf < 4; ++mf)
#pragma unroll
                for (int nf = 0; nf < 4; ++nf)
                    mma_f16(acc[mf][nf], a[mf], &b2[nf >> 1][(nf & 1) * 2]);
        }
    };

    load_chunk(0, 0);
    load_chunk(1, 1);
    int buf = 0;
    for (int c = 0; c < NCHUNK; ++c) {
        if (c + 1 < NCHUNK) CP_WAITG1();
        else                CP_WAIT0();
        __syncthreads();
        if (c + 2 < NCHUNK) load_chunk(c + 2, (buf + 2) % 3);
        compute(buf);
        buf = (buf + 1) % 3;
    }

    if (Mode == 2) {
        // Transposed fp16 epilogue: stage [n][t] in smem, write coalesced rows.
        __syncthreads();                       // pipeline smem now free
        __half* st = (__half*)smf;             // [128 n][PT]
#pragma unroll
        for (int mf = 0; mf < 4; ++mf) {
            const int r0 = wm * 64 + mf * 16 + g;
#pragma unroll
            for (int nf = 0; nf < 4; ++nf) {
                const int c0 = wn * 32 + nf * 8 + tig * 2;
                st[(c0    ) * PT + r0    ] = __float2half_rn(acc[mf][nf][0]);
                st[(c0 + 1) * PT + r0    ] = __float2half_rn(acc[mf][nf][1]);
                st[(c0    ) * PT + r0 + 8] = __float2half_rn(acc[mf][nf][2]);
                st[(c0 + 1) * PT + r0 + 8] = __float2half_rn(acc[mf][nf][3]);
            }
        }
        __syncthreads();
        __half* C = (__half*)Cp;
        const int row  = tid >> 1;             // n_local
        const int toff = (tid & 1) * 64;       // t_local half-range
        const uint4* src = (const uint4*)(st + row * PT + toff);
        uint4* dst = (uint4*)(C + (size_t)row * ldc + toff);
#pragma unroll
        for (int i = 0; i < 8; ++i) dst[i] = src[i];
        return;
    }

#pragma unroll
    for (int mf = 0; mf < 4; ++mf) {
        const int r0 = wm * 64 + mf * 16 + g;
#pragma unroll
        for (int nf = 0; nf < 4; ++nf) {
            const int c0 = wn * 32 + nf * 8 + tig * 2;
            if (Mode == 1) {
                __half* C = (__half*)Cp;
                *(uint32_t*)(C + (size_t)r0 * ldc + c0)       = pack_h2(acc[mf][nf][0], acc[mf][nf][1]);
                *(uint32_t*)(C + (size_t)(r0 + 8) * ldc + c0) = pack_h2(acc[mf][nf][2], acc[mf][nf][3]);
            } else {
                float* C = (float*)Cp;
                *(float2*)(C + (size_t)r0 * ldc + c0)       = make_float2(acc[mf][nf][0], acc[mf][nf][1]);
                *(float2*)(C + (size_t)(r0 + 8) * ldc + c0) = make_float2(acc[mf][nf][2], acc[mf][nf][3]);
            }
        }
    }
}

// QKV: nt 0-15 -> Q, 16-19 -> K, 20-23 -> V (written transposed into vT)
__global__ void __launch_bounds__(256, 2)
gemm_qkv(const __half* __restrict__ x,
         const __half* __restrict__ Wq, const __half* __restrict__ Wk, const __half* __restrict__ Wv,
         __half* __restrict__ q, __half* __restrict__ k, __half* __restrict__ vT)
{
    const int nt = blockIdx.x;
    const int bm = blockIdx.y * GBM;
    if (nt < 16) {
        const int cn = nt * GBN;
        gemm_mma_tile<1>(x + (size_t)bm * KDIM, Wq + (size_t)cn * KDIM,
                         q + (size_t)bm * CC + cn, CC);
    } else if (nt < 20) {
        const int cn = (nt - 16) * GBN;
        gemm_mma_tile<1>(x + (size_t)bm * KDIM, Wk + (size_t)cn * KDIM,
                         k + (size_t)bm * (KVHN * DD) + cn, KVHN * DD);
    } else {
        const int cn = (nt - 20) * GBN;            // col base within [0,512)
        const int bb = bm >> 11;                   // batch
        const int tb = bm & (TT - 1);              // t base
        __half* Cv = vT + ((size_t)(bb * KVHN * DD + cn)) * TT + tb;
        gemm_mma_tile<2>(x + (size_t)bm * KDIM, Wv + (size_t)cn * KDIM, Cv, TT);
    }
}

__global__ void __launch_bounds__(256, 2)
gemm_oproj(const __half* __restrict__ A, const __half* __restrict__ W, float* __restrict__ C)
{
    const int bm = blockIdx.y * GBM;
    const int bn = blockIdx.x * GBN;
    gemm_mma_tile<0>(A + (size_t)bm * KDIM, W + (size_t)bn * KDIM,
                     C + (size_t)bm * CC + bn, CC);
}

// ---------------------------------------------------------------------------
// RoPE in place on K only (fp16 in/out, fp32 math). Q rope fused into flash.
// ---------------------------------------------------------------------------
__global__ void rope_k_kernel(__half* __restrict__ k,
                              const float* __restrict__ cosb, const float* __restrict__ sinb)
{
    const int halfs_k = BB * TT * KVHN * (DD / 2);
    int j = blockIdx.x * blockDim.x + threadIdx.x;
    if (j >= halfs_k) return;
    int d   = j & 31;
    int h   = (j >> 5) & (KVHN - 1);
    int row = j >> 8;
    int t   = row & (TT - 1);
    __half* p = k + (size_t)row * (KVHN * DD) + h * DD;
    float c1 = cosb[t * DD + d],      s1 = sinb[t * DD + d];
    float c2 = cosb[t * DD + d + 32], s2 = sinb[t * DD + d + 32];
    float a = __half2float(p[d]), b2 = __half2float(p[d + 32]);
    p[d]      = __float2half_rn(a * c1 - b2 * s1);
    p[d + 32] = __float2half_rn(b2 * c2 + a * s2);
}

// ---------------------------------------------------------------------------
// fp16 tensor-core flash attention. Causal, GQA G=4, D=64.
// Q rope + 1/sqrt(D) scale fused into the register Q-load.
// ---------------------------------------------------------------------------
#define FQ 128
#define FK 64
#define FST 72
#define FW_K0  0
#define FW_K1  (64 * FST)
#define FW_V0  (2 * 64 * FST)
#define FW_V1  (3 * 64 * FST)
#define FW_P   (4 * 64 * FST)
#define FLASH_SMEM ((4 * 64 * FST + 128 * FST) * 2)   // 55296 B

__global__ void __launch_bounds__(256, 2)
flash_mma(const __half* __restrict__ Qg, const __half* __restrict__ Kg,
          const __half* __restrict__ VTg, __half* __restrict__ Og,
          const float* __restrict__ cosb, const float* __restrict__ sinb)
{
    extern __shared__ float sfraw[];
    __half* sf = (__half*)sfraw;
    const uint32_t sbase = smem_u32(sf);

    const int qt  = (TT / FQ - 1) - blockIdx.x;
    const int h   = blockIdx.y;
    const int b   = blockIdx.z;
    const int kvh = h >> 2;
    const int tid = threadIdx.x;
    const int w   = tid >> 5, lane = tid & 31;
    const int g   = lane >> 2, tig = lane & 3;

    const int lrowA = lane & 15;
    const int lcolA = (lane >> 4) * 16;
    const int lrowB = (lane & 7) + ((lane >> 4) << 3);
    const int lcolB = (lane & 8) ? 16 : 0;

    // ---- Q load with fused RoPE + 0.125 scale ----
    uint32_t qf[4][4];
    {
        const __half* Qb = Qg + ((size_t)(b * TT + qt * FQ + w * 16)) * CC + h * DD;
        uint32_t qr[4][4];
#pragma unroll
        for (int ks = 0; ks < 4; ++ks) {
            qr[ks][0] = *(const uint32_t*)(Qb + (size_t)g * CC + ks * 16 + 2 * tig);
            qr[ks][1] = *(const uint32_t*)(Qb + (size_t)(g + 8) * CC + ks * 16 + 2 * tig);
            qr[ks][2] = *(const uint32_t*)(Qb + (size_t)g * CC + ks * 16 + 2 * tig + 8);
            qr[ks][3] = *(const uint32_t*)(Qb + (size_t)(g + 8) * CC + ks * 16 + 2 * tig + 8);
        }
        const int t0 = qt * FQ + w * 16 + g;
#pragma unroll
        for (int ks = 0; ks < 2; ++ks) {
#pragma unroll
            for (int j = 0; j < 4; ++j) {
                const int t = (j & 1) ? (t0 + 8) : t0;
                const int d = ks * 16 + 2 * tig + ((j >= 2) ? 8 : 0);
                __half2 lo = *reinterpret_cast<__half2*>(&qr[ks][j]);
                __half2 hi = *reinterpret_cast<__half2*>(&qr[ks + 2][j]);
                float a0 = __half2float(lo.x), a1 = __half2float(lo.y);
                float b0 = __half2float(hi.x), b1 = __half2float(hi.y);
                const float* cb = cosb + t * DD;
                const float* sb = sinb + t * DD;
                float c0 = cb[d], c1 = cb[d + 1], s0 = sb[d], s1 = sb[d + 1];
                float C0 = cb[d + 32], C1 = cb[d + 33], S0 = sb[d + 32], S1 = sb[d + 33];
                qf[ks][j]     = pack_h2((a0 * c0 - b0 * s0) * 0.125f,
                                        (a1 * c1 - b1 * s1) * 0.125f);
                qf[ks + 2][j] = pack_h2((b0 * C0 + a0 * S0) * 0.125f,
                                        (b1 * C1 + a1 * S1) * 0.125f);
            }
        }
    }

    float oacc[8][4];
#pragma unroll
    for (int nf = 0; nf < 8; ++nf)
#pragma unroll
        for (int e = 0; e < 4; ++e) oacc[nf][e] = 0.f;
    float m0 = -1e30f, m1 = -1e30f, l0 = 0.f, l1 = 0.f;

    const int ktmax = 2 * qt + 1;
    const __half* VTb = VTg + ((size_t)(b * KVHN + kvh)) * DD * TT;

    auto prefetch = [&](int kt, int buf) {
        const __half* Kb = Kg + ((size_t)(b * TT + kt * FK)) * (KVHN * DD) + kvh * DD;
        const uint32_t kd = sbase + (buf ? FW_K1 : FW_K0) * 2u;
        const uint32_t vd = sbase + (buf ? FW_V1 : FW_V0) * 2u;
#pragma unroll
        for (int i = 0; i < 2; ++i) {
            int lin = tid + i * 256;
            int r = lin >> 3, c8 = lin & 7;
            CP16(kd + (uint32_t)(r * FST + c8 * 8) * 2u, Kb + (size_t)r * (KVHN * DD) + c8 * 8);
            CP16(vd + (uint32_t)(r * FST + c8 * 8) * 2u, VTb + (size_t)r * TT + kt * FK + c8 * 8);
        }
        CP_COMMIT();
    };

    prefetch(0, 0);
    __half* Pw = sf + FW_P + w * 16 * FST;
    const uint32_t paddr = sbase + (uint32_t)(FW_P + w * 16 * FST + lrowA * FST) * 2u + lcolA;

    for (int kt = 0; kt <= ktmax; ++kt) {
        const int buf = kt & 1;
        CP_WAIT0();
        __syncthreads();
        if (kt < ktmax) prefetch(kt + 1, buf ^ 1);

        const uint32_t kbase = sbase + (buf ? FW_K1 : FW_K0) * 2u;
        const uint32_t vbase = sbase + (buf ? FW_V1 : FW_V0) * 2u;

        float sacc[8][4];
#pragma unroll
        for (int nf = 0; nf < 8; ++nf)
#pragma unroll
            for (int e = 0; e < 4; ++e) sacc[nf][e] = 0.f;

#pragma unroll
        for (int ks = 0; ks < 4; ++ks) {
            uint32_t b2[4][4];
#pragma unroll
            for (int np = 0; np < 4; ++np)
                LDMX4(b2[np][0], b2[np][1], b2[np][2], b2[np][3],
                      kbase + (uint32_t)((np * 16 + lrowB) * FST) * 2u + lcolB + ks * 32);
#pragma unroll
            for (int nf = 0; nf < 8; ++nf)
                mma_f16(sacc[nf], qf[ks], &b2[nf >> 1][(nf & 1) * 2]);
        }

        if (kt >= 2 * qt) {
            const int q0 = qt * FQ + w * 16 + g;
            const int q1 = q0 + 8;
#pragma unroll
            for (int nf = 0; nf < 8; ++nf) {
                const int key = kt * FK + nf * 8 + tig * 2;
                if (key     > q0) sacc[nf][0] = -1e30f;
                if (key + 1 > q0) sacc[nf][1] = -1e30f;
                if (key     > q1) sacc[nf][2] = -1e30f;
                if (key + 1 > q1) sacc[nf][3] = -1e30f;
            }
        }

        float mx0 = -1e30f, mx1 = -1e30f;
#pragma unroll
        for (int nf = 0; nf < 8; ++nf) {
            mx0 = fmaxf(mx0, fmaxf(sacc[nf][0], sacc[nf][1]));
            mx1 = fmaxf(mx1, fmaxf(sacc[nf][2], sacc[nf][3]));
        }
        mx0 = fmaxf(mx0, __shfl_xor_sync(0xffffffffu, mx0, 1));
        mx0 = fmaxf(mx0, __shfl_xor_sync(0xffffffffu, mx0, 2));
        mx1 = fmaxf(mx1, __shfl_xor_sync(0xffffffffu, mx1, 1));
        mx1 = fmaxf(mx1, __shfl_xor_sync(0xffffffffu, mx1, 2));

        const float mn0 = fmaxf(m0, mx0), mn1 = fmaxf(m1, mx1);
        const float c0 = __expf(m0 - mn0), c1 = __expf(m1 - mn1);
        float s0 = 0.f, s1 = 0.f;
#pragma unroll
        for (int nf = 0; nf < 8; ++nf) {
            sacc[nf][0] = __expf(sacc[nf][0] - mn0);
            sacc[nf][1] = __expf(sacc[nf][1] - mn0);
            sacc[nf][2] = __expf(sacc[nf][2] - mn1);
            sacc[nf][3] = __expf(sacc[nf][3] - mn1);
            s0 += sacc[nf][0] + sacc[nf][1];
            s1 += sacc[nf][2] + sacc[nf][3];
        }
        s0 += __shfl_xor_sync(0xffffffffu, s0, 1);
        s0 += __shfl_xor_sync(0xffffffffu, s0, 2);
        s1 += __shfl_xor_sync(0xffffffffu, s1, 1);
        s1 += __shfl_xor_sync(0xffffffffu, s1, 2);

        l0 = l0 * c0 + s0;  l1 = l1 * c1 + s1;
        m0 = mn0;           m1 = mn1;
#pragma unroll
        for (int nf = 0; nf < 8; ++nf) {
            oacc[nf][0] *= c0; oacc[nf][1] *= c0;
            oacc[nf][2] *= c1; oacc[nf][3] *= c1;
        }

#pragma unroll
        for (int nf = 0; nf < 8; ++nf) {
            *(uint32_t*)(Pw + g * FST + nf * 8 + tig * 2)       = pack_h2(sacc[nf][0], sacc[nf][1]);
            *(uint32_t*)(Pw + (g + 8) * FST + nf * 8 + tig * 2) = pack_h2(sacc[nf][2], sacc[nf][3]);
        }
        __syncwarp();

#pragma unroll
        for (int ks = 0; ks < 4; ++ks) {
            uint32_t pa[4];
            LDMX4(pa[0], pa[1], pa[2], pa[3], paddr + ks * 32);
            uint32_t b2[4][4];
#pragma unroll
            for (int np = 0; np < 4; ++np)
                LDMX4(b2[np][0], b2[np][1], b2[np][2], b2[np][3],
                      vbase + (uint32_t)((np * 16 + lrowB) * FST) * 2u + lcolB + ks * 32);
#pragma unroll
            for (int nf = 0; nf < 8; ++nf)
                mma_f16(oacc[nf], pa, &b2[nf >> 1][(nf & 1) * 2]);
        }
        __syncwarp();
    }

    __half* Ob = Og + ((size_t)(b * TT + qt * FQ + w * 16)) * CC + h * DD;
    const float i0 = 1.0f / l0, i1 = 1.0f / l1;
#pragma unroll
    for (int nf = 0; nf < 8; ++nf) {
        *(uint32_t*)(Ob + (size_t)g * CC + nf * 8 + tig * 2) =
            pack_h2(oacc[nf][0] * i0, oacc[nf][1] * i0);
        *(uint32_t*)(Ob + (size_t)(g + 8) * CC + nf * 8 + tig * 2) =
            pack_h2(oacc[nf][2] * i1, oacc[nf][3] * i1);
    }
}

// ---------------------------------------------------------------------------
extern "C" void kernel_launch(void* const* d_in, const int* in_sizes, int n_in,
                              void* d_out, int out_size)
{
    const float* x    = (const float*)d_in[0];
    const float* Wq   = (const float*)d_in[1];
    const float* Wk   = (const float*)d_in[2];
    const float* Wv   = (const float*)d_in[3];
    const float* Wo   = (const float*)d_in[4];
    const float* cosb = (const float*)d_in[5];
    const float* sinb = (const float*)d_in[6];
    float* out = (float*)d_out;

    __half *q, *k, *vT, *attn, *xt, *wqt, *wkt, *wvt, *wot;
    cudaGetSymbolAddress((void**)&q,    g_q);
    cudaGetSymbolAddress((void**)&k,    g_k);
    cudaGetSymbolAddress((void**)&vT,   g_vT);
    cudaGetSymbolAddress((void**)&attn, g_attn);
    cudaGetSymbolAddress((void**)&xt,   g_xt);
    cudaGetSymbolAddress((void**)&wqt,  g_wqt);
    cudaGetSymbolAddress((void**)&wkt,  g_wkt);
    cudaGetSymbolAddress((void**)&wvt,  g_wvt);
    cudaGetSymbolAddress((void**)&wot,  g_wot);

    cudaFuncSetAttribute(gemm_qkv,   cudaFuncAttributeMaxDynamicSharedMemorySize, GEMM_SMEM);
    cudaFuncSetAttribute(gemm_oproj, cudaFuncAttributeMaxDynamicSharedMemorySize, GEMM_SMEM);
    cudaFuncSetAttribute(flash_mma,  cudaFuncAttributeMaxDynamicSharedMemorySize, FLASH_SMEM);

    // fp16 pre-rounding copies (one launch)
    {
        const int total = N4_X + 2 * N4_WQ + 2 * N4_WK;
        round_copy_all<<<(total + 255) / 256, 256>>>(
            (const float4*)x,  (uint2*)xt,
            (const float4*)Wq, (uint2*)wqt,
            (const float4*)Wk, (uint2*)wkt,
            (const float4*)Wv, (uint2*)wvt,
            (const float4*)Wo, (uint2*)wot);
    }

    // QKV projections (fp16 mma, BK=64); V written transposed into vT
    gemm_qkv<<<dim3(24, 32), 256, GEMM_SMEM>>>(xt, wqt, wkt, wvt, q, k, vT);

    // RoPE on K only (Q rope fused into flash)
    {
        int total = BB * TT * KVHN * (DD / 2);
        rope_k_kernel<<<(total + 255) / 256, 256>>>(k, cosb, sinb);
    }

    // Flash attention (fused Q rope + scale)
    flash_mma<<<dim3(TT / FQ, HH, BB), 256, FLASH_SMEM>>>(q, k, vT, attn, cosb, sinb);

    // Output projection (fp32 out)
    gemm_oproj<<<dim3(16, 32), 256, GEMM_SMEM>>>(attn, wot, out);
}